// round 4
// baseline (speedup 1.0000x reference)
#include <cuda_runtime.h>

#define NN 100000
#define EE 1600000
#define DIN 128
#define HIDD 64
#define GG 256
#define NLAYERS 3
#define BN_EPS 1e-5f
#define NB_SCAN ((NN + 255) / 256)   // 391
#define LB 782                        // ceil(NN/128)

// ---------------- device scratch (no allocs allowed) ----------------
__device__ __align__(16) int   g_cnt[NN];
__device__ __align__(16) int   g_fill[NN];
__device__ __align__(16) int   g_off[NN + 1];
__device__ __align__(16) int   g_bsum[NB_SCAN];
__device__ __align__(16) int   g_boff[512];
__device__ __align__(16) float g_dinv[NN];
__device__ __align__(16) int   g_src[EE];
__device__ __align__(16) int   g_dst[EE];
__device__ __align__(16) int2  g_csr[EE];      // .x = src, .y = bits(norm)
__device__ __align__(16) int   g_batch[NN];
__device__ __align__(16) float g_h[NN * HIDD]; // node features (fp32)
__device__ __align__(16) float g_gsum[GG * HIDD];
__device__ __align__(16) float g_gcnt[GG];
__device__ int g_is64;

// ---------------- dtype detection ----------------
__global__ void k_detect(const int* __restrict__ ei) {
    int nz = 0;
    for (int i = 0; i < 32; i++) nz |= ei[2 * i + 1];
    g_is64 = (nz == 0) ? 1 : 0;
}

__global__ void k_init() {
    int i = blockIdx.x * blockDim.x + threadIdx.x;
    if (i < NN) { g_cnt[i] = 0; g_fill[i] = 0; }
    if (i < GG * HIDD) g_gsum[i] = 0.f;
    if (i < GG) g_gcnt[i] = 0.f;
    if (i == 0) g_off[NN] = EE;
}

// indices -> int32, in-degree count, per-graph node count
__global__ void k_convert(const int* __restrict__ ei, const int* __restrict__ bt) {
    int i = blockIdx.x * blockDim.x + threadIdx.x;
    const bool is64 = (g_is64 != 0);
    if (i < EE) {
        int s = is64 ? ei[2 * i] : ei[i];
        int d = is64 ? ei[2 * (EE + i)] : ei[EE + i];
        g_src[i] = s;
        g_dst[i] = d;
        atomicAdd(&g_cnt[d], 1);
    }
    if (i < NN) {
        int b = is64 ? bt[2 * i] : bt[i];
        g_batch[i] = b;
        atomicAdd(&g_gcnt[b], 1.f);
    }
}

// ---------------- prefix scan (also emits dinv) ----------------
__global__ void k_scan_block() {
    __shared__ int s[256];
    int b = blockIdx.x, t = threadIdx.x, i = b * 256 + t;
    int v = (i < NN) ? g_cnt[i] : 0;
    if (i < NN) g_dinv[i] = rsqrtf((float)(v + 1));
    s[t] = v; __syncthreads();
#pragma unroll
    for (int o = 1; o < 256; o <<= 1) {
        int x = (t >= o) ? s[t - o] : 0;
        __syncthreads();
        s[t] += x;
        __syncthreads();
    }
    if (i < NN) g_off[i] = s[t] - v;
    if (t == 255) g_bsum[b] = s[255];
}

__global__ void k_scan_top() {
    __shared__ int s[512];
    int t = threadIdx.x;
    int v = (t < NB_SCAN) ? g_bsum[t] : 0;
    s[t] = v; __syncthreads();
#pragma unroll
    for (int o = 1; o < 512; o <<= 1) {
        int x = (t >= o) ? s[t - o] : 0;
        __syncthreads();
        s[t] += x;
        __syncthreads();
    }
    g_boff[t] = s[t] - v;
}

__global__ void k_scan_add() {
    int i = blockIdx.x * blockDim.x + threadIdx.x;
    if (i < NN) g_off[i] += g_boff[i >> 8];
}

__global__ void k_place() {
    int e = blockIdx.x * blockDim.x + threadIdx.x;
    if (e >= EE) return;
    int s = g_src[e], d = g_dst[e];
    float w = g_dinv[s] * g_dinv[d];
    int pos = g_off[d] + atomicAdd(&g_fill[d], 1);
    g_csr[pos] = make_int2(s, __float_as_int(w));
}

// ---------------- input GEMM: h = x[N,128] @ W_in[128,64] + b ----------------
__global__ void k_gemm_in(const float* __restrict__ A, const float* __restrict__ W,
                          const float* __restrict__ bias, float* __restrict__ C) {
    __shared__ float sA[32][68];
    __shared__ float sW[32][68];
    const int m0 = blockIdx.x * 64;
    const int tid = threadIdx.x;
    const int mg = tid / 16;
    const int cg = tid % 16;
    float acc[4][4];
#pragma unroll
    for (int i = 0; i < 4; i++)
#pragma unroll
        for (int j = 0; j < 4; j++) acc[i][j] = 0.f;

    for (int kb = 0; kb < DIN; kb += 32) {
        for (int t = tid; t < 64 * 32; t += 256) {
            int mm = t >> 5, kk = t & 31;
            int node = m0 + mm;
            sA[kk][mm] = (node < NN) ? A[(long)node * DIN + kb + kk] : 0.f;
        }
        for (int t = tid; t < 32 * 64; t += 256) {
            int kk = t >> 6, cc = t & 63;
            sW[kk][cc] = W[(kb + kk) * HIDD + cc];
        }
        __syncthreads();
#pragma unroll
        for (int kk = 0; kk < 32; kk++) {
            float4 aa = *(const float4*)&sA[kk][mg * 4];
            float4 ww = *(const float4*)&sW[kk][cg * 4];
            acc[0][0] += aa.x * ww.x; acc[0][1] += aa.x * ww.y; acc[0][2] += aa.x * ww.z; acc[0][3] += aa.x * ww.w;
            acc[1][0] += aa.y * ww.x; acc[1][1] += aa.y * ww.y; acc[1][2] += aa.y * ww.z; acc[1][3] += aa.y * ww.w;
            acc[2][0] += aa.z * ww.x; acc[2][1] += aa.z * ww.y; acc[2][2] += aa.z * ww.z; acc[2][3] += aa.z * ww.w;
            acc[3][0] += aa.w * ww.x; acc[3][1] += aa.w * ww.y; acc[3][2] += aa.w * ww.z; acc[3][3] += aa.w * ww.w;
        }
        __syncthreads();
    }
    float4 bv = *(const float4*)&bias[cg * 4];
#pragma unroll
    for (int i = 0; i < 4; i++) {
        int node = m0 + mg * 4 + i;
        if (node < NN) {
            float4 o;
            o.x = acc[i][0] + bv.x; o.y = acc[i][1] + bv.y;
            o.z = acc[i][2] + bv.z; o.w = acc[i][3] + bv.w;
            *(float4*)&C[(long)node * HIDD + cg * 4] = o;
        }
    }
}

// ---------------- fused layer: gather(CSR) -> GEMM -> BN -> ReLU -------------
// Block: 128 nodes, 256 threads (8 warps). POOL=1: final layer, epilogue
// accumulates straight into per-graph sums instead of writing h.
template <int POOL>
__global__ void __launch_bounds__(256) k_layer(
        const float* __restrict__ h, const float* __restrict__ W,
        const float* __restrict__ bias, const float* __restrict__ gamma,
        const float* __restrict__ beta, const float* __restrict__ mean,
        const float* __restrict__ var, float* __restrict__ hout) {
    __shared__ float sA[128][66];   // [node][feat], pad 2
    __shared__ float sW[64][68];    // [k][c], pad 4
    const int tid = threadIdx.x;
    const int warp = tid >> 5;
    const int lane = tid & 31;
    const int base = blockIdx.x * 128;

    for (int t = tid; t < 64 * 64; t += 256) sW[t >> 6][t & 63] = W[t];

    // ---- gather phase: warp-per-node, 16 nodes per warp ----
#pragma unroll 1
    for (int j = 0; j < 16; j++) {
        int ln = warp * 16 + j;
        int node = base + ln;
        float2 acc = make_float2(0.f, 0.f);
        if (node < NN) {
            float di = g_dinv[node];
            float sw = di * di;
            float2 self = *(const float2*)&h[(long)node * HIDD + lane * 2];
            acc.x = self.x * sw; acc.y = self.y * sw;
            int e = g_off[node], end = g_off[node + 1];
            for (; e + 1 < end; e += 2) {
                int2 m0 = g_csr[e];
                int2 m1 = g_csr[e + 1];
                float w0 = __int_as_float(m0.y), w1 = __int_as_float(m1.y);
                float2 v0 = *(const float2*)&h[(long)m0.x * HIDD + lane * 2];
                float2 v1 = *(const float2*)&h[(long)m1.x * HIDD + lane * 2];
                acc.x += w0 * v0.x + w1 * v1.x;
                acc.y += w0 * v0.y + w1 * v1.y;
            }
            if (e < end) {
                int2 m = g_csr[e];
                float w = __int_as_float(m.y);
                float2 v = *(const float2*)&h[(long)m.x * HIDD + lane * 2];
                acc.x += w * v.x;
                acc.y += w * v.y;
            }
        }
        *(float2*)&sA[ln][lane * 2] = acc;
    }
    __syncthreads();

    // ---- GEMM phase: thread = 8 nodes x 4 cols ----
    const int mg = tid >> 4;
    const int cg = tid & 15;
    float acc[8][4];
#pragma unroll
    for (int i = 0; i < 8; i++)
#pragma unroll
        for (int j = 0; j < 4; j++) acc[i][j] = 0.f;

#pragma unroll 8
    for (int kk = 0; kk < 64; kk++) {
        float4 w = *(const float4*)&sW[kk][cg * 4];
        float a[8];
#pragma unroll
        for (int i = 0; i < 8; i++) a[i] = sA[mg * 8 + i][kk];
#pragma unroll
        for (int i = 0; i < 8; i++) {
            acc[i][0] += a[i] * w.x;
            acc[i][1] += a[i] * w.y;
            acc[i][2] += a[i] * w.z;
            acc[i][3] += a[i] * w.w;
        }
    }

    // epilogue: bias + BN + ReLU
    float4 bv = *(const float4*)&bias[cg * 4];
    float4 gm = *(const float4*)&gamma[cg * 4];
    float4 be = *(const float4*)&beta[cg * 4];
    float4 mn = *(const float4*)&mean[cg * 4];
    float4 vr = *(const float4*)&var[cg * 4];
    float sc0 = gm.x * rsqrtf(vr.x + BN_EPS), sh0 = be.x - mn.x * sc0;
    float sc1 = gm.y * rsqrtf(vr.y + BN_EPS), sh1 = be.y - mn.y * sc1;
    float sc2 = gm.z * rsqrtf(vr.z + BN_EPS), sh2 = be.z - mn.z * sc2;
    float sc3 = gm.w * rsqrtf(vr.w + BN_EPS), sh3 = be.w - mn.w * sc3;
#pragma unroll
    for (int i = 0; i < 8; i++) {
        int node = base + mg * 8 + i;
        if (node < NN) {
            float4 o;
            o.x = fmaxf((acc[i][0] + bv.x) * sc0 + sh0, 0.f);
            o.y = fmaxf((acc[i][1] + bv.y) * sc1 + sh1, 0.f);
            o.z = fmaxf((acc[i][2] + bv.z) * sc2 + sh2, 0.f);
            o.w = fmaxf((acc[i][3] + bv.w) * sc3 + sh3, 0.f);
            if (POOL) {
                int b = g_batch[node];
                atomicAdd((float4*)&g_gsum[b * HIDD + cg * 4], o);
            } else {
                *(float4*)&hout[(long)node * HIDD + cg * 4] = o;
            }
        }
    }
}

// ---------------- MLP head ----------------
__global__ void k_mlp(const float* __restrict__ W1, const float* __restrict__ b1,
                      const float* __restrict__ W2, const float* __restrict__ b2,
                      const float* __restrict__ W3, const float* __restrict__ b3,
                      float* __restrict__ out) {
    __shared__ float v[64], a1[64], a2[32];
    int g = blockIdx.x;
    int c = threadIdx.x;
    float cnt = fmaxf(g_gcnt[g], 1.f);
    v[c] = g_gsum[g * HIDD + c] / cnt;
    __syncthreads();
    float s = b1[c];
#pragma unroll
    for (int k = 0; k < 64; k++) s += v[k] * W1[k * 64 + c];
    a1[c] = fmaxf(s, 0.f);
    __syncthreads();
    if (c < 32) {
        float s2 = b2[c];
#pragma unroll
        for (int k = 0; k < 64; k++) s2 += a1[k] * W2[k * 32 + c];
        a2[c] = fmaxf(s2, 0.f);
    }
    __syncthreads();
    if (c < 32) {
        float p = a2[c] * W3[c];
#pragma unroll
        for (int o = 16; o > 0; o >>= 1) p += __shfl_down_sync(0xffffffff, p, o);
        if (c == 0) out[g] = p + b3[0];
    }
}

// ---------------- launch ----------------
extern "C" void kernel_launch(void* const* d_in, const int* in_sizes, int n_in,
                              void* d_out, int out_size) {
    const float* x      = (const float*)d_in[0];
    const int*   ei     = (const int*)d_in[1];
    const int*   bt     = (const int*)d_in[2];
    const float* W_in   = (const float*)d_in[3];
    const float* b_in   = (const float*)d_in[4];
    const float* conv_W = (const float*)d_in[5];
    const float* conv_b = (const float*)d_in[6];
    const float* gamma  = (const float*)d_in[7];
    const float* beta   = (const float*)d_in[8];
    const float* mean   = (const float*)d_in[9];
    const float* var    = (const float*)d_in[10];
    const float* W1     = (const float*)d_in[11];
    const float* b1     = (const float*)d_in[12];
    const float* W2     = (const float*)d_in[13];
    const float* b2     = (const float*)d_in[14];
    const float* W3     = (const float*)d_in[15];
    const float* b3     = (const float*)d_in[16];
    float* out = (float*)d_out;

    float* p_h = nullptr;
    cudaGetSymbolAddress((void**)&p_h, g_h);

    k_detect<<<1, 1>>>(ei);
    k_init<<<(NN + 255) / 256, 256>>>();
    k_convert<<<(EE + 255) / 256, 256>>>(ei, bt);
    k_scan_block<<<NB_SCAN, 256>>>();
    k_scan_top<<<1, 512>>>();
    k_scan_add<<<(NN + 255) / 256, 256>>>();
    k_place<<<(EE + 255) / 256, 256>>>();

    k_gemm_in<<<(NN + 63) / 64, 256>>>(x, W_in, b_in, p_h);

    for (int l = 0; l < NLAYERS; l++) {
        const float* Wl = conv_W + (long)l * HIDD * HIDD;
        if (l < NLAYERS - 1)
            k_layer<0><<<LB, 256>>>(p_h, Wl, conv_b + l * HIDD, gamma + l * HIDD,
                                    beta + l * HIDD, mean + l * HIDD, var + l * HIDD, p_h);
        else
            k_layer<1><<<LB, 256>>>(p_h, Wl, conv_b + l * HIDD, gamma + l * HIDD,
                                    beta + l * HIDD, mean + l * HIDD, var + l * HIDD, p_h);
    }

    k_mlp<<<GG, 64>>>(W1, b1, W2, b2, W3, b3, out);
}

// round 5
// speedup vs baseline: 1.1883x; 1.1883x over previous
#include <cuda_runtime.h>
#include <cuda_fp16.h>

#define NN 100000
#define EE 1600000
#define DIN 128
#define HIDD 64
#define GG 256
#define NLAYERS 3
#define BN_EPS 1e-5f
#define NB_SCAN ((NN + 255) / 256)   // 391

// ---------------- device scratch (no allocs allowed) ----------------
__device__ __align__(16) int    g_cnt[NN];
__device__ __align__(16) int    g_fill[NN];
__device__ __align__(16) int    g_off[NN + 1];
__device__ __align__(16) int    g_bsum[NB_SCAN];
__device__ __align__(16) int    g_boff[512];
__device__ __align__(16) float  g_dinv[NN];
__device__ __align__(16) int    g_src[EE];
__device__ __align__(16) int    g_dst[EE];
__device__ __align__(16) int2   g_csr[EE];       // .x = src, .y = bits(norm)
__device__ __align__(16) int    g_batch[NN];
__device__ __align__(16) __half g_h[NN * HIDD];  // node features (fp16 storage)
__device__ __align__(16) float  g_a[NN * HIDD];  // aggregated features (fp32)
__device__ __align__(16) float  g_gsum[GG * HIDD];
__device__ __align__(16) float  g_gcnt[GG];
__device__ int g_is64;

struct alignas(8) HalfQuad { __half2 a, b; };

// ---------------- dtype detection ----------------
__global__ void k_detect(const int* __restrict__ ei) {
    int nz = 0;
    for (int i = 0; i < 32; i++) nz |= ei[2 * i + 1];
    g_is64 = (nz == 0) ? 1 : 0;
}

__global__ void k_init() {
    int i = blockIdx.x * blockDim.x + threadIdx.x;
    if (i < NN) { g_cnt[i] = 0; g_fill[i] = 0; }
    if (i < GG * HIDD) g_gsum[i] = 0.f;
    if (i < GG) g_gcnt[i] = 0.f;
    if (i == 0) g_off[NN] = EE;
}

// indices -> int32, in-degree count, per-graph node count
__global__ void k_convert(const int* __restrict__ ei, const int* __restrict__ bt) {
    int i = blockIdx.x * blockDim.x + threadIdx.x;
    const bool is64 = (g_is64 != 0);
    if (i < EE) {
        int s = is64 ? ei[2 * i] : ei[i];
        int d = is64 ? ei[2 * (EE + i)] : ei[EE + i];
        g_src[i] = s;
        g_dst[i] = d;
        atomicAdd(&g_cnt[d], 1);
    }
    if (i < NN) {
        int b = is64 ? bt[2 * i] : bt[i];
        g_batch[i] = b;
        atomicAdd(&g_gcnt[b], 1.f);
    }
}

// ---------------- prefix scan (also emits dinv) ----------------
__global__ void k_scan_block() {
    __shared__ int s[256];
    int b = blockIdx.x, t = threadIdx.x, i = b * 256 + t;
    int v = (i < NN) ? g_cnt[i] : 0;
    if (i < NN) g_dinv[i] = rsqrtf((float)(v + 1));
    s[t] = v; __syncthreads();
#pragma unroll
    for (int o = 1; o < 256; o <<= 1) {
        int x = (t >= o) ? s[t - o] : 0;
        __syncthreads();
        s[t] += x;
        __syncthreads();
    }
    if (i < NN) g_off[i] = s[t] - v;
    if (t == 255) g_bsum[b] = s[255];
}

__global__ void k_scan_top() {
    __shared__ int s[512];
    int t = threadIdx.x;
    int v = (t < NB_SCAN) ? g_bsum[t] : 0;
    s[t] = v; __syncthreads();
#pragma unroll
    for (int o = 1; o < 512; o <<= 1) {
        int x = (t >= o) ? s[t - o] : 0;
        __syncthreads();
        s[t] += x;
        __syncthreads();
    }
    g_boff[t] = s[t] - v;
}

__global__ void k_scan_add() {
    int i = blockIdx.x * blockDim.x + threadIdx.x;
    if (i < NN) g_off[i] += g_boff[i >> 8];
}

__global__ void k_place() {
    int e = blockIdx.x * blockDim.x + threadIdx.x;
    if (e >= EE) return;
    int s = g_src[e], d = g_dst[e];
    float w = g_dinv[s] * g_dinv[d];
    int pos = g_off[d] + atomicAdd(&g_fill[d], 1);
    g_csr[pos] = make_int2(s, __float_as_int(w));
}

// ---------------- gather: a[i] = sum norm*h[src] + dinv^2*h[i]  (fp16 in, fp32 out)
__global__ void k_gather(const __half* __restrict__ h, float* __restrict__ a) {
    int gw = (blockIdx.x * blockDim.x + threadIdx.x) >> 5;
    int lane = threadIdx.x & 31;
    if (gw >= NN) return;
    float di = g_dinv[gw];
    float sw = di * di;
    float2 self = __half22float2(*(const __half2*)&h[(long)gw * HIDD + lane * 2]);
    float2 acc;
    acc.x = self.x * sw; acc.y = self.y * sw;
    int e = g_off[gw], end = g_off[gw + 1];
    for (; e + 1 < end; e += 2) {
        int2 m0 = g_csr[e];
        int2 m1 = g_csr[e + 1];
        float w0 = __int_as_float(m0.y), w1 = __int_as_float(m1.y);
        float2 v0 = __half22float2(*(const __half2*)&h[(long)m0.x * HIDD + lane * 2]);
        float2 v1 = __half22float2(*(const __half2*)&h[(long)m1.x * HIDD + lane * 2]);
        acc.x += w0 * v0.x + w1 * v1.x;
        acc.y += w0 * v0.y + w1 * v1.y;
    }
    if (e < end) {
        int2 m = g_csr[e];
        float w = __int_as_float(m.y);
        float2 v = __half22float2(*(const __half2*)&h[(long)m.x * HIDD + lane * 2]);
        acc.x += w * v.x;
        acc.y += w * v.y;
    }
    *(float2*)&a[(long)gw * HIDD + lane * 2] = acc;
}

// ---------------- tiled GEMM: fp32 A[N,K] @ W[K,64], epilogue variants -------
// FUSE: +bias,BN,ReLU.  POOL: accumulate into per-graph sums (no h write).
// Otherwise write fp16 h.
template <int K, int FUSE, int POOL>
__global__ void k_gemm(const float* __restrict__ A, const float* __restrict__ W,
                       const float* __restrict__ bias,
                       const float* __restrict__ gamma, const float* __restrict__ beta,
                       const float* __restrict__ mean, const float* __restrict__ var,
                       __half* __restrict__ C) {
    __shared__ float sA[32][68];
    __shared__ float sW[32][68];
    const int m0 = blockIdx.x * 64;
    const int tid = threadIdx.x;
    const int mg = tid / 16;
    const int cg = tid % 16;
    float acc[4][4];
#pragma unroll
    for (int i = 0; i < 4; i++)
#pragma unroll
        for (int j = 0; j < 4; j++) acc[i][j] = 0.f;

    for (int kb = 0; kb < K; kb += 32) {
        for (int t = tid; t < 64 * 32; t += 256) {
            int mm = t >> 5, kk = t & 31;
            int node = m0 + mm;
            sA[kk][mm] = (node < NN) ? A[(long)node * K + kb + kk] : 0.f;
        }
        for (int t = tid; t < 32 * 64; t += 256) {
            int kk = t >> 6, cc = t & 63;
            sW[kk][cc] = W[(kb + kk) * HIDD + cc];
        }
        __syncthreads();
#pragma unroll
        for (int kk = 0; kk < 32; kk++) {
            float4 aa = *(const float4*)&sA[kk][mg * 4];
            float4 ww = *(const float4*)&sW[kk][cg * 4];
            acc[0][0] += aa.x * ww.x; acc[0][1] += aa.x * ww.y; acc[0][2] += aa.x * ww.z; acc[0][3] += aa.x * ww.w;
            acc[1][0] += aa.y * ww.x; acc[1][1] += aa.y * ww.y; acc[1][2] += aa.y * ww.z; acc[1][3] += aa.y * ww.w;
            acc[2][0] += aa.z * ww.x; acc[2][1] += aa.z * ww.y; acc[2][2] += aa.z * ww.z; acc[2][3] += aa.z * ww.w;
            acc[3][0] += aa.w * ww.x; acc[3][1] += aa.w * ww.y; acc[3][2] += aa.w * ww.z; acc[3][3] += aa.w * ww.w;
        }
        __syncthreads();
    }
    float4 bv = *(const float4*)&bias[cg * 4];
    float sc[4] = {1.f, 1.f, 1.f, 1.f}, sh[4] = {0.f, 0.f, 0.f, 0.f};
    if (FUSE) {
        float4 gm = *(const float4*)&gamma[cg * 4];
        float4 be = *(const float4*)&beta[cg * 4];
        float4 mn = *(const float4*)&mean[cg * 4];
        float4 vr = *(const float4*)&var[cg * 4];
        sc[0] = gm.x * rsqrtf(vr.x + BN_EPS); sh[0] = be.x - mn.x * sc[0];
        sc[1] = gm.y * rsqrtf(vr.y + BN_EPS); sh[1] = be.y - mn.y * sc[1];
        sc[2] = gm.z * rsqrtf(vr.z + BN_EPS); sh[2] = be.z - mn.z * sc[2];
        sc[3] = gm.w * rsqrtf(vr.w + BN_EPS); sh[3] = be.w - mn.w * sc[3];
    }
#pragma unroll
    for (int i = 0; i < 4; i++) {
        int node = m0 + mg * 4 + i;
        if (node < NN) {
            float o[4] = {acc[i][0] + bv.x, acc[i][1] + bv.y,
                          acc[i][2] + bv.z, acc[i][3] + bv.w};
            if (FUSE) {
#pragma unroll
                for (int j = 0; j < 4; j++) o[j] = fmaxf(o[j] * sc[j] + sh[j], 0.f);
            }
            if (POOL) {
                int b = g_batch[node];
                atomicAdd((float4*)&g_gsum[b * HIDD + cg * 4],
                          make_float4(o[0], o[1], o[2], o[3]));
            } else {
                HalfQuad q;
                q.a = __floats2half2_rn(o[0], o[1]);
                q.b = __floats2half2_rn(o[2], o[3]);
                *(HalfQuad*)&C[(long)node * HIDD + cg * 4] = q;
            }
        }
    }
}

// ---------------- MLP head ----------------
__global__ void k_mlp(const float* __restrict__ W1, const float* __restrict__ b1,
                      const float* __restrict__ W2, const float* __restrict__ b2,
                      const float* __restrict__ W3, const float* __restrict__ b3,
                      float* __restrict__ out) {
    __shared__ float v[64], a1[64], a2[32];
    int g = blockIdx.x;
    int c = threadIdx.x;
    float cnt = fmaxf(g_gcnt[g], 1.f);
    v[c] = g_gsum[g * HIDD + c] / cnt;
    __syncthreads();
    float s = b1[c];
#pragma unroll
    for (int k = 0; k < 64; k++) s += v[k] * W1[k * 64 + c];
    a1[c] = fmaxf(s, 0.f);
    __syncthreads();
    if (c < 32) {
        float s2 = b2[c];
#pragma unroll
        for (int k = 0; k < 64; k++) s2 += a1[k] * W2[k * 32 + c];
        a2[c] = fmaxf(s2, 0.f);
    }
    __syncthreads();
    if (c < 32) {
        float p = a2[c] * W3[c];
#pragma unroll
        for (int o = 16; o > 0; o >>= 1) p += __shfl_down_sync(0xffffffff, p, o);
        if (c == 0) out[g] = p + b3[0];
    }
}

// ---------------- launch ----------------
extern "C" void kernel_launch(void* const* d_in, const int* in_sizes, int n_in,
                              void* d_out, int out_size) {
    const float* x      = (const float*)d_in[0];
    const int*   ei     = (const int*)d_in[1];
    const int*   bt     = (const int*)d_in[2];
    const float* W_in   = (const float*)d_in[3];
    const float* b_in   = (const float*)d_in[4];
    const float* conv_W = (const float*)d_in[5];
    const float* conv_b = (const float*)d_in[6];
    const float* gamma  = (const float*)d_in[7];
    const float* beta   = (const float*)d_in[8];
    const float* mean   = (const float*)d_in[9];
    const float* var    = (const float*)d_in[10];
    const float* W1     = (const float*)d_in[11];
    const float* b1     = (const float*)d_in[12];
    const float* W2     = (const float*)d_in[13];
    const float* b2     = (const float*)d_in[14];
    const float* W3     = (const float*)d_in[15];
    const float* b3     = (const float*)d_in[16];
    float* out = (float*)d_out;

    __half* p_h = nullptr;
    float*  p_a = nullptr;
    cudaGetSymbolAddress((void**)&p_h, g_h);
    cudaGetSymbolAddress((void**)&p_a, g_a);

    k_detect<<<1, 1>>>(ei);
    k_init<<<(NN + 255) / 256, 256>>>();
    k_convert<<<(EE + 255) / 256, 256>>>(ei, bt);
    k_scan_block<<<NB_SCAN, 256>>>();
    k_scan_top<<<1, 512>>>();
    k_scan_add<<<(NN + 255) / 256, 256>>>();
    k_place<<<(EE + 255) / 256, 256>>>();

    const int gemm_blocks = (NN + 63) / 64;
    const int gather_blocks = (NN * 32 + 255) / 256;

    // h0 = fp16(x @ W_in + b_in)
    k_gemm<DIN, 0, 0><<<gemm_blocks, 256>>>(x, W_in, b_in,
                                            nullptr, nullptr, nullptr, nullptr, p_h);

    for (int l = 0; l < NLAYERS; l++) {
        const float* Wl = conv_W + (long)l * HIDD * HIDD;
        k_gather<<<gather_blocks, 256>>>(p_h, p_a);
        if (l < NLAYERS - 1)
            k_gemm<HIDD, 1, 0><<<gemm_blocks, 256>>>(p_a, Wl, conv_b + l * HIDD,
                                                     gamma + l * HIDD, beta + l * HIDD,
                                                     mean + l * HIDD, var + l * HIDD, p_h);
        else
            k_gemm<HIDD, 1, 1><<<gemm_blocks, 256>>>(p_a, Wl, conv_b + l * HIDD,
                                                     gamma + l * HIDD, beta + l * HIDD,
                                                     mean + l * HIDD, var + l * HIDD, p_h);
    }

    k_mlp<<<GG, 64>>>(W1, b1, W2, b2, W3, b3, out);
}